// round 11
// baseline (speedup 1.0000x reference)
#include <cuda_runtime.h>
#include <cuda_bf16.h>
#include <cuda_fp16.h>
#include <math.h>
#include <stdint.h>

#define Bq   128
#define Sq   512
#define Dq   768
#define NHq  8
#define HDq  96
#define HIDq 384
#define Cq   768            // NH*HD
#define Mq   (Bq*Sq)        // 65536 tokens

// ---------------------------------------------------------------------------
// Scratch (__device__ globals; cudaMalloc is forbidden)
// ---------------------------------------------------------------------------
__device__ __half  g_Xh [(size_t)Mq * Dq];   // 96 MB X fp16
__device__ __half  g_Ph [(size_t)Cq * Dq];   // P fp16
__device__ __half  g_W1b[(size_t)NHq * HIDq * HDq];
__device__ __half  g_W2b[(size_t)NHq * HDq * HIDq];
__device__ float   g_part[(size_t)(Mq/128) * 3 * Cq];  // [mtile][{m,l,a}][768]

// ---------------------------------------------------------------------------
// Generic-PTX tensor-core helpers (plain sm_103 target safe)
// ---------------------------------------------------------------------------
__device__ __forceinline__ uint32_t smem_u32(const void* p) {
    uint32_t a;
    asm("{ .reg .u64 t; cvta.to.shared.u64 t, %1; cvt.u32.u64 %0, t; }"
        : "=r"(a) : "l"(p));
    return a;
}
__device__ __forceinline__ void mma16816(float* c, const uint32_t* a, const uint32_t* b) {
    asm volatile("mma.sync.aligned.m16n8k16.row.col.f32.f16.f16.f32 "
        "{%0,%1,%2,%3}, {%4,%5,%6,%7}, {%8,%9}, {%0,%1,%2,%3};"
        : "+f"(c[0]), "+f"(c[1]), "+f"(c[2]), "+f"(c[3])
        : "r"(a[0]), "r"(a[1]), "r"(a[2]), "r"(a[3]), "r"(b[0]), "r"(b[1]));
}
__device__ __forceinline__ void ldsm_x4(uint32_t* r, uint32_t addr) {
    asm volatile("ldmatrix.sync.aligned.m8n8.x4.shared.b16 {%0,%1,%2,%3}, [%4];"
        : "=r"(r[0]), "=r"(r[1]), "=r"(r[2]), "=r"(r[3]) : "r"(addr));
}
__device__ __forceinline__ void cp16(uint32_t dst, const void* src) {
    asm volatile("cp.async.cg.shared.global [%0], [%1], 16;" :: "r"(dst), "l"(src));
}
#define CP_COMMIT()  asm volatile("cp.async.commit_group;" ::: "memory")
#define CP_WAIT(n)   asm volatile("cp.async.wait_group %0;" :: "n"(n) : "memory")
#define SW(o)        ((o) ^ (((o) >> 3) & 0x70))

__device__ __forceinline__ float fexp(float x) {
    x = fmaxf(x, -80.f);
    float t  = x * 1.4426950408889634f;
    float fi = floorf(t);
    float f  = t - fi;
    float p  = 1.8775767e-3f;
    p = fmaf(p, f, 8.9893397e-3f);
    p = fmaf(p, f, 5.5826318e-2f);
    p = fmaf(p, f, 2.4015361e-1f);
    p = fmaf(p, f, 6.9315308e-1f);
    p = fmaf(p, f, 1.0f);
    return __int_as_float(__float_as_int(p) + (((int)fi) << 23));
}

// ---------------------------------------------------------------------------
// K0a: X fp32 -> fp16 convert
// ---------------------------------------------------------------------------
__global__ __launch_bounds__(256) void k0_cvtX(
    const float* __restrict__ src, int n4)
{
    int i = blockIdx.x * 256 + threadIdx.x;
    if (i >= n4) return;
    float4 v = reinterpret_cast<const float4*>(src)[i];
    ushort4 H;
    H.x = __half_as_ushort(__float2half_rn(v.x));
    H.y = __half_as_ushort(__float2half_rn(v.y));
    H.z = __half_as_ushort(__float2half_rn(v.z));
    H.w = __half_as_ushort(__float2half_rn(v.w));
    reinterpret_cast<ushort4*>(g_Xh)[i] = H;
}

// ---------------------------------------------------------------------------
// K0b: P + W1 + W2 fp32 -> fp16 convert in one launch
// ---------------------------------------------------------------------------
#define N4P (Cq * Dq / 4)
#define N4W (NHq * HIDq * HDq / 4)

__global__ __launch_bounds__(256) void k0_misc(
    const float* __restrict__ P, const float* __restrict__ W1,
    const float* __restrict__ W2)
{
    int i = blockIdx.x * 256 + threadIdx.x;
    const float* src;
    __half* dst;
    if (i < N4P)            { src = P;  dst = g_Ph; }
    else {
        i -= N4P;
        if (i < N4W)        { src = W1; dst = g_W1b; }
        else                { i -= N4W; if (i >= N4W) return; src = W2; dst = g_W2b; }
    }
    float4 v = reinterpret_cast<const float4*>(src)[i];
    ushort4 H;
    H.x = __half_as_ushort(__float2half_rn(v.x));
    H.y = __half_as_ushort(__float2half_rn(v.y));
    H.z = __half_as_ushort(__float2half_rn(v.z));
    H.w = __half_as_ushort(__float2half_rn(v.w));
    reinterpret_cast<ushort4*>(dst)[i] = H;
}

// ---------------------------------------------------------------------------
// KF: fully fused per-(head, 128-token tile) kernel — fp16, 512 threads.
//   16 warps: 8 m-groups (16 rows each) x 2 n-halves. Same tiles/pipeline/
//   smem plan as R10; per-warp work halved for 4-warps-per-SMSP latency hiding.
// ---------------------------------------------------------------------------
#define OHH   0
#define OAS   26624
#define OMK   76288
#define ORD   76800         // reduce scratch [4][3][96] fp32 = 4608
#define OST   81408
#define ASTG  28672         // stage: Xh 16384 | Ph 12288
#define OF    OST
#define OW1   (OST + 34816)
#define OW2   (OST + 88064)
#define W1SZ  26624
#define W2SZ  26112
#define KF_SMEM 221696
#define SHI   208
#define SF    272
#define NT    512

__global__ __launch_bounds__(NT, 1) void kf_fused(
    const __half* __restrict__ Xh, const __half* __restrict__ Ph,
    const float* __restrict__ bP,
    const float* __restrict__ b1, const float* __restrict__ b2,
    const float* __restrict__ mask)
{
    extern __shared__ char smem[];
    const uint32_t sb = smem_u32(smem);
    const int tid = threadIdx.x, wid = tid >> 5, lane = tid & 31;
    const int head  = blockIdx.x;
    const int mt    = blockIdx.y;
    const int mtile = mt * 128;
    const int batch = mt >> 2;
    const int soff  = (mt & 3) * 128;
    const int wm  = (wid >> 1) * 16;   // 8 m-groups of 16 rows
    const int wnA = (wid & 1) * 48;    // phase A / layer2 N split
    const int wn1 = (wid & 1) * 64;    // layer1 N split

    const __half* W1h = g_W1b + (size_t)head * HIDq * HDq;
    const __half* W2h = g_W2b + (size_t)head * HDq * HIDq;
    const float* b1h = b1 + head * HIDq;
    const float* b2h = b2 + head * HDq;

    // ======================= Phase A: projection GEMM ======================
    auto load_chunk = [&](int c, int s) {
        const int kb = c * 64;
        const uint32_t st = sb + OST + s * ASTG;
        #pragma unroll
        for (int t = 0; t < 2; t++) {              // X: 1024 cells of 16B
            int idx = tid + t * NT;
            int row = idx >> 3, c16 = idx & 7;
            uint32_t off = SW(row * 128 + c16 * 16);
            cp16(st + off, Xh + (size_t)(mtile + row) * Dq + kb + c16 * 8);
        }
        {                                          // P: 768 cells of 16B
            int idx = tid;
            int row = idx >> 3, c16 = idx & 7;
            if (idx < 768) {
                uint32_t off = SW(row * 128 + c16 * 16);
                cp16(st + 16384 + off, Ph + (size_t)(head * HDq + row) * Dq + kb + c16 * 8);
            }
            idx = tid + NT;
            if (idx < 768) {
                int row2 = idx >> 3, c2 = idx & 7;
                uint32_t off = SW(row2 * 128 + c2 * 16);
                cp16(st + 16384 + off, Ph + (size_t)(head * HDq + row2) * Dq + kb + c2 * 8);
            }
        }
        CP_COMMIT();
    };

    float accA[6][4];
    #pragma unroll
    for (int b = 0; b < 6; b++)
        #pragma unroll
        for (int c = 0; c < 4; c++) accA[b][c] = 0.f;

    load_chunk(0, 0);
    #pragma unroll 1
    for (int c = 0; c < 12; c++) {
        if (c + 1 < 12) { load_chunk(c + 1, (c + 1) & 1); CP_WAIT(1); }
        else            { CP_WAIT(0); }
        __syncthreads();

        const uint32_t st  = sb + OST + (c & 1) * ASTG;
        const uint32_t sXh = st, sPh = st + 16384;
        #pragma unroll
        for (int ks = 0; ks < 4; ks++) {
            uint32_t ah[4], bh[3][4];
            {
                int row = wm + (lane & 15);
                ldsm_x4(ah, sXh + SW(row * 128 + ((lane >> 4) + ks * 2) * 16));
            }
            #pragma unroll
            for (int p = 0; p < 3; p++) {
                int g = lane >> 3;
                int row = wnA + p * 16 + (g >> 1) * 8 + (lane & 7);
                ldsm_x4(bh[p], sPh + SW(row * 128 + (ks * 2 + (g & 1)) * 16));
            }
            #pragma unroll
            for (int nf = 0; nf < 6; nf++)
                mma16816(accA[nf], ah, &bh[nf >> 1][(nf & 1) * 2]);
        }
        __syncthreads();      // all MMAs on this stage done before overwrite
    }

    // W chunk prefetch (stage buffers dead; W dbuf overlaps them)
    auto load_w = [&](int jc) {
        const int j0 = jc * 128;
        const uint32_t w1d = sb + OW1 + (jc & 1) * W1SZ;
        const uint32_t w2d = sb + OW2 + (jc & 1) * W2SZ;
        #pragma unroll
        for (int t = 0; t < 3; t++) {              // W1: 1536 cells
            int idx = tid + t * NT;
            int row = idx / 12, c16 = idx % 12;
            cp16(w1d + row * SHI + c16 * 16, W1h + (size_t)(j0 + row) * HDq + c16 * 8);
        }
        #pragma unroll
        for (int t = 0; t < 3; t++) {              // W2: 1536 cells
            int idx = tid + t * NT;
            int row = idx >> 4, c16 = idx & 15;
            cp16(w2d + row * SF + c16 * 16, W2h + (size_t)row * HIDq + j0 + c16 * 8);
        }
        CP_COMMIT();
    };
    load_w(0);

    // Phase A epilogue: accA + bias -> Hi fp16 (OHH) and Hi fp32 (OAS)
    float* As = reinterpret_cast<float*>(smem + OAS);
    float* mk = reinterpret_cast<float*>(smem + OMK);
    {
        const int m0 = wm + (lane >> 2);
        #pragma unroll
        for (int nf = 0; nf < 6; nf++) {
            const int n = wnA + nf * 8 + 2 * (lane & 3);
            const float c0 = __ldg(&bP[head * HDq + n]);
            const float c1 = __ldg(&bP[head * HDq + n + 1]);
            float v0 = accA[nf][0] + c0, v1 = accA[nf][1] + c1;
            float v2 = accA[nf][2] + c0, v3 = accA[nf][3] + c1;
            __half2 p0 = __floats2half2_rn(v0, v1);
            __half2 p1 = __floats2half2_rn(v2, v3);
            *reinterpret_cast<uint32_t*>(smem + OHH + m0 * SHI + n * 2) =
                *reinterpret_cast<uint32_t*>(&p0);
            *reinterpret_cast<uint32_t*>(smem + OHH + (m0 + 8) * SHI + n * 2) =
                *reinterpret_cast<uint32_t*>(&p1);
            As[m0 * 97 + n]           = v0;
            As[m0 * 97 + n + 1]       = v1;
            As[(m0 + 8) * 97 + n]     = v2;
            As[(m0 + 8) * 97 + n + 1] = v3;
        }
    }
    if (tid < 128) mk[tid] = mask[batch * Sq + soff + tid];
    __syncthreads();

    // ========================== Phase B: MLP ===============================
    float acc2[6][4];
    #pragma unroll
    for (int b = 0; b < 6; b++)
        #pragma unroll
        for (int c = 0; c < 4; c++) acc2[b][c] = 0.f;

    #pragma unroll 1
    for (int jc = 0; jc < 3; jc++) {
        const int j0 = jc * 128;
        CP_WAIT(0);
        __syncthreads();
        if (jc + 1 < 3) load_w(jc + 1);

        const uint32_t w1b = sb + OW1 + (jc & 1) * W1SZ;
        const uint32_t w2b = sb + OW2 + (jc & 1) * W2SZ;

        float acc1[8][4];
        #pragma unroll
        for (int b = 0; b < 8; b++)
            #pragma unroll
            for (int c = 0; c < 4; c++) acc1[b][c] = 0.f;

        #pragma unroll
        for (int ks = 0; ks < 6; ks++) {       // K = 96
            uint32_t afr[4], bfr[4][4];
            {
                int row = wm + (lane & 15);
                ldsm_x4(afr, sb + OHH + row * SHI + (lane >> 4) * 16 + ks * 32);
            }
            #pragma unroll
            for (int p = 0; p < 4; p++) {
                int g = lane >> 3;
                int row = wn1 + p * 16 + (g >> 1) * 8 + (lane & 7);
                ldsm_x4(bfr[p], w1b + row * SHI + (g & 1) * 16 + ks * 32);
            }
            #pragma unroll
            for (int nf = 0; nf < 8; nf++)
                mma16816(acc1[nf], afr, &bfr[nf >> 1][(nf & 1) * 2]);
        }

        // relu + b1 -> F (fp16)
        {
            const int m0 = wm + (lane >> 2);
            #pragma unroll
            for (int nf = 0; nf < 8; nf++) {
                const int jl = wn1 + nf * 8 + 2 * (lane & 3);
                const float c0 = __ldg(&b1h[j0 + jl]), c1 = __ldg(&b1h[j0 + jl + 1]);
                float v0 = fmaxf(acc1[nf][0] + c0, 0.f);
                float v1 = fmaxf(acc1[nf][1] + c1, 0.f);
                float v2 = fmaxf(acc1[nf][2] + c0, 0.f);
                float v3 = fmaxf(acc1[nf][3] + c1, 0.f);
                __half2 p0 = __floats2half2_rn(v0, v1);
                __half2 p1 = __floats2half2_rn(v2, v3);
                *reinterpret_cast<uint32_t*>(smem + OF + m0 * SF + jl * 2) =
                    *reinterpret_cast<uint32_t*>(&p0);
                *reinterpret_cast<uint32_t*>(smem + OF + (m0 + 8) * SF + jl * 2) =
                    *reinterpret_cast<uint32_t*>(&p1);
            }
        }
        __syncthreads();

        #pragma unroll
        for (int ks = 0; ks < 8; ks++) {       // K = 128
            uint32_t afr[4], bfr[3][4];
            {
                int row = wm + (lane & 15);
                ldsm_x4(afr, sb + OF + row * SF + (lane >> 4) * 16 + ks * 32);
            }
            #pragma unroll
            for (int p = 0; p < 3; p++) {
                int g = lane >> 3;
                int row = wnA + p * 16 + (g >> 1) * 8 + (lane & 7);
                ldsm_x4(bfr[p], w2b + row * SF + (g & 1) * 16 + ks * 32);
            }
            #pragma unroll
            for (int nf = 0; nf < 6; nf++)
                mma16816(acc2[nf], afr, &bfr[nf >> 1][(nf & 1) * 2]);
        }
    }

    // ===================== Phase C: softmax-pool partials ==================
    __syncthreads();
    float* Lg = reinterpret_cast<float*>(smem + OW1);   // logits [128][97]
    {
        const int m0 = wm + (lane >> 2);
        #pragma unroll
        for (int nf = 0; nf < 6; nf++) {
            const int n = wnA + nf * 8 + 2 * (lane & 3);
            const float c0 = __ldg(&b2h[n]), c1 = __ldg(&b2h[n + 1]);
            Lg[m0 * 97 + n]           = acc2[nf][0] + c0;
            Lg[m0 * 97 + n + 1]       = acc2[nf][1] + c1;
            Lg[(m0 + 8) * 97 + n]     = acc2[nf][2] + c0;
            Lg[(m0 + 8) * 97 + n + 1] = acc2[nf][3] + c1;
        }
    }
    __syncthreads();

    float* red = reinterpret_cast<float*>(smem + ORD);  // [4][3][96]
    if (tid < 384) {
        const int ch = tid % 96, q = tid / 96;
        float m = -1e30f, l = 0.f, a = 0.f;
        for (int t = q * 32; t < q * 32 + 32; t++) {
            if (mk[t] > 0.5f) {
                float x  = Lg[t * 97 + ch];
                float hv = As[t * 97 + ch];
                float n  = fmaxf(m, x);
                float sc = fexp(m - n), w = fexp(x - n);
                l = fmaf(l, sc, w);
                a = fmaf(a, sc, w * hv);
                m = n;
            }
        }
        red[(q * 3 + 0) * 96 + ch] = m;
        red[(q * 3 + 1) * 96 + ch] = l;
        red[(q * 3 + 2) * 96 + ch] = a;
    }
    __syncthreads();
    if (tid < 96) {
        const int ch = tid;
        float m = -1e30f;
        #pragma unroll
        for (int q = 0; q < 4; q++)
            m = fmaxf(m, red[(q * 3 + 0) * 96 + ch]);
        float l = 0.f, a = 0.f;
        #pragma unroll
        for (int q = 0; q < 4; q++) {
            float s = fexp(red[(q * 3 + 0) * 96 + ch] - m);
            l = fmaf(red[(q * 3 + 1) * 96 + ch], s, l);
            a = fmaf(red[(q * 3 + 2) * 96 + ch], s, a);
        }
        float* dst = &g_part[(size_t)mt * 3 * Cq + head * HDq + ch];
        dst[0]      = m;
        dst[Cq]     = l;
        dst[2 * Cq] = a;
    }
}

// ---------------------------------------------------------------------------
// K3: merge 4 chunk partials per (batch, channel) -> output
// ---------------------------------------------------------------------------
__global__ __launch_bounds__(256) void k3_reduce(float* __restrict__ out)
{
    const int idx = blockIdx.x * 256 + threadIdx.x;
    const int b = idx / Cq, ch = idx % Cq;

    float m = -1e30f;
    #pragma unroll
    for (int c = 0; c < 4; c++)
        m = fmaxf(m, g_part[(size_t)(b * 4 + c) * 3 * Cq + ch]);

    float l = 0.f, a = 0.f;
    #pragma unroll
    for (int c = 0; c < 4; c++) {
        const float* p = &g_part[(size_t)(b * 4 + c) * 3 * Cq + ch];
        float s = fexp(p[0] - m);
        l = fmaf(p[Cq],     s, l);
        a = fmaf(p[2 * Cq], s, a);
    }
    out[idx] = a / l;
}

// ---------------------------------------------------------------------------
extern "C" void kernel_launch(void* const* d_in, const int* in_sizes, int n_in,
                              void* d_out, int out_size)
{
    const float* X    = (const float*)d_in[0];
    const float* mask = (const float*)d_in[1];
    const float* P    = (const float*)d_in[2];
    const float* bP   = (const float*)d_in[3];
    const float* W1   = (const float*)d_in[4];
    const float* b1   = (const float*)d_in[5];
    const float* W2   = (const float*)d_in[6];
    const float* b2   = (const float*)d_in[7];
    float* out = (float*)d_out;

    cudaFuncSetAttribute(kf_fused, cudaFuncAttributeMaxDynamicSharedMemorySize, KF_SMEM);

    __half *Xh, *Ph;
    cudaGetSymbolAddress((void**)&Xh, g_Xh);
    cudaGetSymbolAddress((void**)&Ph, g_Ph);

    // K0a: X convert to fp16
    {
        int n4x = Mq * Dq / 4;
        k0_cvtX<<<(n4x + 255) / 256, 256>>>(X, n4x);
    }
    // K0b: P + W converts in one launch
    {
        int ncells = N4P + 2 * N4W;
        k0_misc<<<(ncells + 255) / 256, 256>>>(P, W1, W2);
    }

    // KF: fused projection + MLP + partial softmax-pool
    dim3 gf(NHq, Mq / 128);
    kf_fused<<<gf, NT, KF_SMEM>>>(Xh, Ph, bP, b1, b2, mask);

    // K3: merge partials
    k3_reduce<<<(Bq * Cq) / 256, 256>>>(out);
}

// round 13
// speedup vs baseline: 1.0494x; 1.0494x over previous
#include <cuda_runtime.h>
#include <cuda_bf16.h>
#include <cuda_fp16.h>
#include <math.h>
#include <stdint.h>

#define Bq   128
#define Sq   512
#define Dq   768
#define NHq  8
#define HDq  96
#define HIDq 384
#define Cq   768            // NH*HD
#define Mq   (Bq*Sq)        // 65536 tokens

// ---------------------------------------------------------------------------
// Scratch (__device__ globals; cudaMalloc is forbidden)
// ---------------------------------------------------------------------------
__device__ __half  g_Xh [(size_t)Mq * Dq];   // 96 MB X fp16
__device__ __half  g_Ph [(size_t)Cq * Dq];   // P fp16
__device__ __half  g_W1b[(size_t)NHq * HIDq * HDq];
__device__ __half  g_W2b[(size_t)NHq * HDq * HIDq];
__device__ float   g_part[(size_t)(Mq/128) * 3 * Cq];  // [mtile][{m,l,a}][768]

// ---------------------------------------------------------------------------
// Generic-PTX tensor-core helpers (plain sm_103 target safe)
// ---------------------------------------------------------------------------
__device__ __forceinline__ uint32_t smem_u32(const void* p) {
    uint32_t a;
    asm("{ .reg .u64 t; cvta.to.shared.u64 t, %1; cvt.u32.u64 %0, t; }"
        : "=r"(a) : "l"(p));
    return a;
}
__device__ __forceinline__ void mma16816(float* c, const uint32_t* a, const uint32_t* b) {
    asm volatile("mma.sync.aligned.m16n8k16.row.col.f32.f16.f16.f32 "
        "{%0,%1,%2,%3}, {%4,%5,%6,%7}, {%8,%9}, {%0,%1,%2,%3};"
        : "+f"(c[0]), "+f"(c[1]), "+f"(c[2]), "+f"(c[3])
        : "r"(a[0]), "r"(a[1]), "r"(a[2]), "r"(a[3]), "r"(b[0]), "r"(b[1]));
}
__device__ __forceinline__ void ldsm_x4(uint32_t* r, uint32_t addr) {
    asm volatile("ldmatrix.sync.aligned.m8n8.x4.shared.b16 {%0,%1,%2,%3}, [%4];"
        : "=r"(r[0]), "=r"(r[1]), "=r"(r[2]), "=r"(r[3]) : "r"(addr));
}
__device__ __forceinline__ void cp16(uint32_t dst, const void* src) {
    asm volatile("cp.async.cg.shared.global [%0], [%1], 16;" :: "r"(dst), "l"(src));
}
#define CP_COMMIT()  asm volatile("cp.async.commit_group;" ::: "memory")
#define CP_WAIT(n)   asm volatile("cp.async.wait_group %0;" :: "n"(n) : "memory")
#define SW(o)        ((o) ^ (((o) >> 3) & 0x70))

__device__ __forceinline__ float fexp(float x) {
    x = fmaxf(x, -80.f);
    float t  = x * 1.4426950408889634f;
    float fi = floorf(t);
    float f  = t - fi;
    float p  = 1.8775767e-3f;
    p = fmaf(p, f, 8.9893397e-3f);
    p = fmaf(p, f, 5.5826318e-2f);
    p = fmaf(p, f, 2.4015361e-1f);
    p = fmaf(p, f, 6.9315308e-1f);
    p = fmaf(p, f, 1.0f);
    return __int_as_float(__float_as_int(p) + (((int)fi) << 23));
}

// ---------------------------------------------------------------------------
// K0a: X fp32 -> fp16 convert
// ---------------------------------------------------------------------------
__global__ __launch_bounds__(256) void k0_cvtX(
    const float* __restrict__ src, int n4)
{
    int i = blockIdx.x * 256 + threadIdx.x;
    if (i >= n4) return;
    float4 v = reinterpret_cast<const float4*>(src)[i];
    ushort4 H;
    H.x = __half_as_ushort(__float2half_rn(v.x));
    H.y = __half_as_ushort(__float2half_rn(v.y));
    H.z = __half_as_ushort(__float2half_rn(v.z));
    H.w = __half_as_ushort(__float2half_rn(v.w));
    reinterpret_cast<ushort4*>(g_Xh)[i] = H;
}

// ---------------------------------------------------------------------------
// K0b: P + W1 + W2 fp32 -> fp16 convert in one launch
// ---------------------------------------------------------------------------
#define N4P (Cq * Dq / 4)
#define N4W (NHq * HIDq * HDq / 4)

__global__ __launch_bounds__(256) void k0_misc(
    const float* __restrict__ P, const float* __restrict__ W1,
    const float* __restrict__ W2)
{
    int i = blockIdx.x * 256 + threadIdx.x;
    const float* src;
    __half* dst;
    if (i < N4P)            { src = P;  dst = g_Ph; }
    else {
        i -= N4P;
        if (i < N4W)        { src = W1; dst = g_W1b; }
        else                { i -= N4W; if (i >= N4W) return; src = W2; dst = g_W2b; }
    }
    float4 v = reinterpret_cast<const float4*>(src)[i];
    ushort4 H;
    H.x = __half_as_ushort(__float2half_rn(v.x));
    H.y = __half_as_ushort(__float2half_rn(v.y));
    H.z = __half_as_ushort(__float2half_rn(v.z));
    H.w = __half_as_ushort(__float2half_rn(v.w));
    reinterpret_cast<ushort4*>(dst)[i] = H;
}

// ---------------------------------------------------------------------------
// KF: fully fused per-(head, 128-token tile) kernel — fp16, 256 threads,
//     3-stage single-sync Phase A pipeline (wait counts CORRECTED).
// ---------------------------------------------------------------------------
#define OHH   0
#define OAS   26624
#define OMK   76288
#define ORD   76800
#define OST   79104
#define ASTG  28672          // stage: Xh 16384 | Ph 12288 ; 3 stages = 86016
#define OF    OST
#define OW1   (OST + 34816)
#define OW2   (OST + 88064)
#define W1SZ  26624
#define W2SZ  26112
#define KF_SMEM 219392
#define SHI   208
#define SF    272

__global__ __launch_bounds__(256, 1) void kf_fused(
    const __half* __restrict__ Xh, const __half* __restrict__ Ph,
    const float* __restrict__ bP,
    const float* __restrict__ b1, const float* __restrict__ b2,
    const float* __restrict__ mask)
{
    extern __shared__ char smem[];
    const uint32_t sb = smem_u32(smem);
    const int tid = threadIdx.x, wid = tid >> 5, lane = tid & 31;
    const int head  = blockIdx.x;
    const int mt    = blockIdx.y;
    const int mtile = mt * 128;
    const int batch = mt >> 2;
    const int soff  = (mt & 3) * 128;
    const int wm  = (wid >> 1) * 32;
    const int wnA = (wid & 1) * 48;
    const int wn1 = (wid & 1) * 64;

    const __half* W1h = g_W1b + (size_t)head * HIDq * HDq;
    const __half* W2h = g_W2b + (size_t)head * HDq * HIDq;
    const float* b1h = b1 + head * HIDq;
    const float* b2h = b2 + head * HDq;

    // ======================= Phase A: projection GEMM ======================
    // 3-stage pipeline, one __syncthreads per chunk.
    // At iteration c: committed groups are 0..c+1, so chunk c resident
    // requires CP_WAIT(1) (only c+1 may remain in flight).
    auto load_chunk = [&](int c, int s) {
        const int kb = c * 64;
        const uint32_t st = sb + OST + s * ASTG;
        #pragma unroll
        for (int t = 0; t < 4; t++) {              // X: 128 rows x 8 col16
            int idx = tid + t * 256;
            int row = idx >> 3, c16 = idx & 7;
            uint32_t off = SW(row * 128 + c16 * 16);
            cp16(st + off, Xh + (size_t)(mtile + row) * Dq + kb + c16 * 8);
        }
        #pragma unroll
        for (int t = 0; t < 3; t++) {              // P: 96 rows x 8 col16
            int idx = tid + t * 256;
            int row = idx >> 3, c16 = idx & 7;
            uint32_t off = SW(row * 128 + c16 * 16);
            cp16(st + 16384 + off, Ph + (size_t)(head * HDq + row) * Dq + kb + c16 * 8);
        }
        CP_COMMIT();
    };

    float accA[2][6][4];
    #pragma unroll
    for (int a = 0; a < 2; a++)
        #pragma unroll
        for (int b = 0; b < 6; b++)
            #pragma unroll
            for (int c = 0; c < 4; c++) accA[a][b][c] = 0.f;

    load_chunk(0, 0);
    load_chunk(1, 1);
    #pragma unroll 1
    for (int c = 0; c < 12; c++) {
        if (c < 11) { CP_WAIT(1); }   // chunk c landed; c+1 may be in flight
        else        { CP_WAIT(0); }
        __syncthreads();   // (a) stage c visible; (b) compute(c-1) reads done
        if (c + 2 < 12) load_chunk(c + 2, (c + 2) % 3);

        const uint32_t st  = sb + OST + (c % 3) * ASTG;
        const uint32_t sXh = st, sPh = st + 16384;
        #pragma unroll
        for (int ks = 0; ks < 4; ks++) {
            uint32_t ah[2][4], bh[3][4];
            #pragma unroll
            for (int mf = 0; mf < 2; mf++) {
                int row = wm + mf * 16 + (lane & 15);
                ldsm_x4(ah[mf], sXh + SW(row * 128 + ((lane >> 4) + ks * 2) * 16));
            }
            #pragma unroll
            for (int p = 0; p < 3; p++) {
                int g = lane >> 3;
                int row = wnA + p * 16 + (g >> 1) * 8 + (lane & 7);
                ldsm_x4(bh[p], sPh + SW(row * 128 + (ks * 2 + (g & 1)) * 16));
            }
            #pragma unroll
            for (int mf = 0; mf < 2; mf++)
                #pragma unroll
                for (int nf = 0; nf < 6; nf++)
                    mma16816(accA[mf][nf], ah[mf], &bh[nf >> 1][(nf & 1) * 2]);
        }
    }
    __syncthreads();       // final chunk's reads done before OST reuse by W dbuf

    // W chunk prefetch (stage buffers dead; W dbuf overlaps them)
    auto load_w = [&](int jc) {
        const int j0 = jc * 128;
        const uint32_t w1d = sb + OW1 + (jc & 1) * W1SZ;
        const uint32_t w2d = sb + OW2 + (jc & 1) * W2SZ;
        #pragma unroll
        for (int t = 0; t < 6; t++) {
            int idx = tid + t * 256;
            int row = idx / 12, c16 = idx % 12;
            cp16(w1d + row * SHI + c16 * 16, W1h + (size_t)(j0 + row) * HDq + c16 * 8);
        }
        #pragma unroll
        for (int t = 0; t < 6; t++) {
            int idx = tid + t * 256;
            int row = idx >> 4, c16 = idx & 15;
            cp16(w2d + row * SF + c16 * 16, W2h + (size_t)row * HIDq + j0 + c16 * 8);
        }
        CP_COMMIT();
    };
    load_w(0);

    // Phase A epilogue: accA + bias -> Hi fp16 (OHH) and Hi fp32 (OAS)
    float* As = reinterpret_cast<float*>(smem + OAS);
    float* mk = reinterpret_cast<float*>(smem + OMK);
    #pragma unroll
    for (int mf = 0; mf < 2; mf++) {
        const int m0 = wm + mf * 16 + (lane >> 2);
        #pragma unroll
        for (int nf = 0; nf < 6; nf++) {
            const int n = wnA + nf * 8 + 2 * (lane & 3);
            const float c0 = __ldg(&bP[head * HDq + n]);
            const float c1 = __ldg(&bP[head * HDq + n + 1]);
            float v0 = accA[mf][nf][0] + c0, v1 = accA[mf][nf][1] + c1;
            float v2 = accA[mf][nf][2] + c0, v3 = accA[mf][nf][3] + c1;
            __half2 p0 = __floats2half2_rn(v0, v1);
            __half2 p1 = __floats2half2_rn(v2, v3);
            *reinterpret_cast<uint32_t*>(smem + OHH + m0 * SHI + n * 2) =
                *reinterpret_cast<uint32_t*>(&p0);
            *reinterpret_cast<uint32_t*>(smem + OHH + (m0 + 8) * SHI + n * 2) =
                *reinterpret_cast<uint32_t*>(&p1);
            As[m0 * 97 + n]           = v0;
            As[m0 * 97 + n + 1]       = v1;
            As[(m0 + 8) * 97 + n]     = v2;
            As[(m0 + 8) * 97 + n + 1] = v3;
        }
    }
    if (tid < 128) mk[tid] = mask[batch * Sq + soff + tid];
    __syncthreads();

    // ========================== Phase B: MLP ===============================
    float acc2[2][6][4];
    #pragma unroll
    for (int a = 0; a < 2; a++)
        #pragma unroll
        for (int b = 0; b < 6; b++)
            #pragma unroll
            for (int c = 0; c < 4; c++) acc2[a][b][c] = 0.f;

    #pragma unroll 1
    for (int jc = 0; jc < 3; jc++) {
        const int j0 = jc * 128;
        CP_WAIT(0);
        __syncthreads();
        if (jc + 1 < 3) load_w(jc + 1);

        const uint32_t w1b = sb + OW1 + (jc & 1) * W1SZ;
        const uint32_t w2b = sb + OW2 + (jc & 1) * W2SZ;

        float acc1[2][8][4];
        #pragma unroll
        for (int a = 0; a < 2; a++)
            #pragma unroll
            for (int b = 0; b < 8; b++)
                #pragma unroll
                for (int c = 0; c < 4; c++) acc1[a][b][c] = 0.f;

        #pragma unroll
        for (int ks = 0; ks < 6; ks++) {       // K = 96
            uint32_t afr[2][4], bfr[4][4];
            #pragma unroll
            for (int mf = 0; mf < 2; mf++) {
                int row = wm + mf * 16 + (lane & 15);
                ldsm_x4(afr[mf], sb + OHH + row * SHI + (lane >> 4) * 16 + ks * 32);
            }
            #pragma unroll
            for (int p = 0; p < 4; p++) {
                int g = lane >> 3;
                int row = wn1 + p * 16 + (g >> 1) * 8 + (lane & 7);
                ldsm_x4(bfr[p], w1b + row * SHI + (g & 1) * 16 + ks * 32);
            }
            #pragma unroll
            for (int mf = 0; mf < 2; mf++)
                #pragma unroll
                for (int nf = 0; nf < 8; nf++)
                    mma16816(acc1[mf][nf], afr[mf], &bfr[nf >> 1][(nf & 1) * 2]);
        }

        // relu + b1 -> F (fp16)
        #pragma unroll
        for (int mf = 0; mf < 2; mf++) {
            const int m0 = wm + mf * 16 + (lane >> 2);
            #pragma unroll
            for (int nf = 0; nf < 8; nf++) {
                const int jl = wn1 + nf * 8 + 2 * (lane & 3);
                const float c0 = __ldg(&b1h[j0 + jl]), c1 = __ldg(&b1h[j0 + jl + 1]);
                float v0 = fmaxf(acc1[mf][nf][0] + c0, 0.f);
                float v1 = fmaxf(acc1[mf][nf][1] + c1, 0.f);
                float v2 = fmaxf(acc1[mf][nf][2] + c0, 0.f);
                float v3 = fmaxf(acc1[mf][nf][3] + c1, 0.f);
                __half2 p0 = __floats2half2_rn(v0, v1);
                __half2 p1 = __floats2half2_rn(v2, v3);
                *reinterpret_cast<uint32_t*>(smem + OF + m0 * SF + jl * 2) =
                    *reinterpret_cast<uint32_t*>(&p0);
                *reinterpret_cast<uint32_t*>(smem + OF + (m0 + 8) * SF + jl * 2) =
                    *reinterpret_cast<uint32_t*>(&p1);
            }
        }
        __syncthreads();

        #pragma unroll
        for (int ks = 0; ks < 8; ks++) {       // K = 128
            uint32_t afr[2][4], bfr[3][4];
            #pragma unroll
            for (int mf = 0; mf < 2; mf++) {
                int row = wm + mf * 16 + (lane & 15);
                ldsm_x4(afr[mf], sb + OF + row * SF + (lane >> 4) * 16 + ks * 32);
            }
            #pragma unroll
            for (int p = 0; p < 3; p++) {
                int g = lane >> 3;
                int row = wnA + p * 16 + (g >> 1) * 8 + (lane & 7);
                ldsm_x4(bfr[p], w2b + row * SF + (g & 1) * 16 + ks * 32);
            }
            #pragma unroll
            for (int mf = 0; mf < 2; mf++)
                #pragma unroll
                for (int nf = 0; nf < 6; nf++)
                    mma16816(acc2[mf][nf], afr[mf], &bfr[nf >> 1][(nf & 1) * 2]);
        }
    }

    // ===================== Phase C: softmax-pool partials (FROZEN) =========
    __syncthreads();
    float* Lg = reinterpret_cast<float*>(smem + OW1);   // logits [128][97]
    #pragma unroll
    for (int mf = 0; mf < 2; mf++) {
        const int m0 = wm + mf * 16 + (lane >> 2);
        #pragma unroll
        for (int nf = 0; nf < 6; nf++) {
            const int n = wnA + nf * 8 + 2 * (lane & 3);
            const float c0 = __ldg(&b2h[n]), c1 = __ldg(&b2h[n + 1]);
            Lg[m0 * 97 + n]           = acc2[mf][nf][0] + c0;
            Lg[m0 * 97 + n + 1]       = acc2[mf][nf][1] + c1;
            Lg[(m0 + 8) * 97 + n]     = acc2[mf][nf][2] + c0;
            Lg[(m0 + 8) * 97 + n + 1] = acc2[mf][nf][3] + c1;
        }
    }
    __syncthreads();

    float* red = reinterpret_cast<float*>(smem + ORD);
    if (tid < 192) {
        const int ch = tid % 96, half = tid / 96;
        float m = -1e30f, l = 0.f, a = 0.f;
        for (int t = half * 64; t < half * 64 + 64; t++) {
            if (mk[t] > 0.5f) {
                float x  = Lg[t * 97 + ch];
                float hv = As[t * 97 + ch];
                float n  = fmaxf(m, x);
                float sc = fexp(m - n), w = fexp(x - n);
                l = fmaf(l, sc, w);
                a = fmaf(a, sc, w * hv);
                m = n;
            }
        }
        red[(half * 3 + 0) * 96 + ch] = m;
        red[(half * 3 + 1) * 96 + ch] = l;
        red[(half * 3 + 2) * 96 + ch] = a;
    }
    __syncthreads();
    if (tid < 96) {
        const int ch = tid;
        float m0 = red[0 * 96 + ch], l0 = red[1 * 96 + ch], a0 = red[2 * 96 + ch];
        float m1 = red[3 * 96 + ch], l1 = red[4 * 96 + ch], a1 = red[5 * 96 + ch];
        float n  = fmaxf(fmaxf(m0, m1), -1e30f);
        float s0 = fexp(m0 - n), s1 = fexp(m1 - n);
        float* dst = &g_part[(size_t)mt * 3 * Cq + head * HDq + ch];
        dst[0]      = n;
        dst[Cq]     = l0 * s0 + l1 * s1;
        dst[2 * Cq] = a0 * s0 + a1 * s1;
    }
}

// ---------------------------------------------------------------------------
// K3: merge 4 chunk partials per (batch, channel) -> output
// ---------------------------------------------------------------------------
__global__ __launch_bounds__(256) void k3_reduce(float* __restrict__ out)
{
    const int idx = blockIdx.x * 256 + threadIdx.x;
    const int b = idx / Cq, ch = idx % Cq;

    float m = -1e30f;
    #pragma unroll
    for (int c = 0; c < 4; c++)
        m = fmaxf(m, g_part[(size_t)(b * 4 + c) * 3 * Cq + ch]);

    float l = 0.f, a = 0.f;
    #pragma unroll
    for (int c = 0; c < 4; c++) {
        const float* p = &g_part[(size_t)(b * 4 + c) * 3 * Cq + ch];
        float s = fexp(p[0] - m);
        l = fmaf(p[Cq],     s, l);
        a = fmaf(p[2 * Cq], s, a);
    }
    out[idx] = a / l;
}

// ---------------------------------------------------------------------------
extern "C" void kernel_launch(void* const* d_in, const int* in_sizes, int n_in,
                              void* d_out, int out_size)
{
    const float* X    = (const float*)d_in[0];
    const float* mask = (const float*)d_in[1];
    const float* P    = (const float*)d_in[2];
    const float* bP   = (const float*)d_in[3];
    const float* W1   = (const float*)d_in[4];
    const float* b1   = (const float*)d_in[5];
    const float* W2   = (const float*)d_in[6];
    const float* b2   = (const float*)d_in[7];
    float* out = (float*)d_out;

    cudaFuncSetAttribute(kf_fused, cudaFuncAttributeMaxDynamicSharedMemorySize, KF_SMEM);

    __half *Xh, *Ph;
    cudaGetSymbolAddress((void**)&Xh, g_Xh);
    cudaGetSymbolAddress((void**)&Ph, g_Ph);

    // K0a: X convert to fp16
    {
        int n4x = Mq * Dq / 4;
        k0_cvtX<<<(n4x + 255) / 256, 256>>>(X, n4x);
    }
    // K0b: P + W converts in one launch
    {
        int ncells = N4P + 2 * N4W;
        k0_misc<<<(ncells + 255) / 256, 256>>>(P, W1, W2);
    }

    // KF: fused projection + MLP + partial softmax-pool
    dim3 gf(NHq, Mq / 128);
    kf_fused<<<gf, 256, KF_SMEM>>>(Xh, Ph, bP, b1, b2, mask);

    // K3: merge partials
    k3_reduce<<<(Bq * Cq) / 256, 256>>>(out);
}

// round 14
// speedup vs baseline: 1.1490x; 1.0949x over previous
#include <cuda_runtime.h>
#include <cuda_bf16.h>
#include <cuda_fp16.h>
#include <math.h>
#include <stdint.h>

#define Bq   128
#define Sq   512
#define Dq   768
#define NHq  8
#define HDq  96
#define HIDq 384
#define Cq   768            // NH*HD
#define Mq   (Bq*Sq)        // 65536 tokens

// ---------------------------------------------------------------------------
// Scratch (__device__ globals; cudaMalloc is forbidden)
// ---------------------------------------------------------------------------
__device__ __half  g_Xh [(size_t)Mq * Dq];   // 96 MB X fp16
__device__ __half  g_Ph [(size_t)Cq * Dq];   // P fp16
__device__ __half  g_W1b[(size_t)NHq * HIDq * HDq];
__device__ __half  g_W2b[(size_t)NHq * HDq * HIDq];
__device__ float   g_part[(size_t)(Mq/128) * 3 * Cq];  // [mtile][{m,l,a}][768]

// ---------------------------------------------------------------------------
// Generic-PTX tensor-core helpers (plain sm_103 target safe)
// ---------------------------------------------------------------------------
__device__ __forceinline__ uint32_t smem_u32(const void* p) {
    uint32_t a;
    asm("{ .reg .u64 t; cvta.to.shared.u64 t, %1; cvt.u32.u64 %0, t; }"
        : "=r"(a) : "l"(p));
    return a;
}
__device__ __forceinline__ void mma16816(float* c, const uint32_t* a, const uint32_t* b) {
    asm volatile("mma.sync.aligned.m16n8k16.row.col.f32.f16.f16.f32 "
        "{%0,%1,%2,%3}, {%4,%5,%6,%7}, {%8,%9}, {%0,%1,%2,%3};"
        : "+f"(c[0]), "+f"(c[1]), "+f"(c[2]), "+f"(c[3])
        : "r"(a[0]), "r"(a[1]), "r"(a[2]), "r"(a[3]), "r"(b[0]), "r"(b[1]));
}
__device__ __forceinline__ void ldsm_x4(uint32_t* r, uint32_t addr) {
    asm volatile("ldmatrix.sync.aligned.m8n8.x4.shared.b16 {%0,%1,%2,%3}, [%4];"
        : "=r"(r[0]), "=r"(r[1]), "=r"(r[2]), "=r"(r[3]) : "r"(addr));
}
__device__ __forceinline__ void cp16(uint32_t dst, const void* src) {
    asm volatile("cp.async.cg.shared.global [%0], [%1], 16;" :: "r"(dst), "l"(src));
}
#define CP_COMMIT()  asm volatile("cp.async.commit_group;" ::: "memory")
#define CP_WAIT(n)   asm volatile("cp.async.wait_group %0;" :: "n"(n) : "memory")
#define SW(o)        ((o) ^ (((o) >> 3) & 0x70))

__device__ __forceinline__ float fexp(float x) {
    x = fmaxf(x, -80.f);
    float t  = x * 1.4426950408889634f;
    float fi = floorf(t);
    float f  = t - fi;
    float p  = 1.8775767e-3f;
    p = fmaf(p, f, 8.9893397e-3f);
    p = fmaf(p, f, 5.5826318e-2f);
    p = fmaf(p, f, 2.4015361e-1f);
    p = fmaf(p, f, 6.9315308e-1f);
    p = fmaf(p, f, 1.0f);
    return __int_as_float(__float_as_int(p) + (((int)fi) << 23));
}

// ---------------------------------------------------------------------------
// K0a: X fp32 -> fp16 convert
// ---------------------------------------------------------------------------
__global__ __launch_bounds__(256) void k0_cvtX(
    const float* __restrict__ src, int n4)
{
    int i = blockIdx.x * 256 + threadIdx.x;
    if (i >= n4) return;
    float4 v = reinterpret_cast<const float4*>(src)[i];
    ushort4 H;
    H.x = __half_as_ushort(__float2half_rn(v.x));
    H.y = __half_as_ushort(__float2half_rn(v.y));
    H.z = __half_as_ushort(__float2half_rn(v.z));
    H.w = __half_as_ushort(__float2half_rn(v.w));
    reinterpret_cast<ushort4*>(g_Xh)[i] = H;
}

// ---------------------------------------------------------------------------
// K0b: P + W1 + W2 fp32 -> fp16 convert in one launch
// ---------------------------------------------------------------------------
#define N4P (Cq * Dq / 4)
#define N4W (NHq * HIDq * HDq / 4)

__global__ __launch_bounds__(256) void k0_misc(
    const float* __restrict__ P, const float* __restrict__ W1,
    const float* __restrict__ W2)
{
    int i = blockIdx.x * 256 + threadIdx.x;
    const float* src;
    __half* dst;
    if (i < N4P)            { src = P;  dst = g_Ph; }
    else {
        i -= N4P;
        if (i < N4W)        { src = W1; dst = g_W1b; }
        else                { i -= N4W; if (i >= N4W) return; src = W2; dst = g_W2b; }
    }
    float4 v = reinterpret_cast<const float4*>(src)[i];
    ushort4 H;
    H.x = __half_as_ushort(__float2half_rn(v.x));
    H.y = __half_as_ushort(__float2half_rn(v.y));
    H.z = __half_as_ushort(__float2half_rn(v.z));
    H.w = __half_as_ushort(__float2half_rn(v.w));
    reinterpret_cast<ushort4*>(dst)[i] = H;
}

// ---------------------------------------------------------------------------
// KF: fully fused per-(head, 128-token tile) kernel — R10 body (fp16, 256
// threads, 2-stage Phase A) + PREFIX-MASK EARLY EXIT: a chunk whose first
// token is masked is fully masked (mask is a prefix mask) -> write trivial
// partials (m=-1e30, l=0, a=0) and return, skipping both GEMMs.
// ---------------------------------------------------------------------------
#define OHH   0
#define OAS   26624
#define OMK   76288
#define ORD   76800
#define OST   79104
#define ASTG  28672          // stage: Xh 16384 | Ph 12288
#define OF    OST
#define OW1   (OST + 34816)
#define OW2   (OST + 88064)
#define W1SZ  26624
#define W2SZ  26112
#define KF_SMEM 219392
#define SHI   208
#define SF    272

__global__ __launch_bounds__(256, 1) void kf_fused(
    const __half* __restrict__ Xh, const __half* __restrict__ Ph,
    const float* __restrict__ bP,
    const float* __restrict__ b1, const float* __restrict__ b2,
    const float* __restrict__ mask)
{
    extern __shared__ char smem[];
    const uint32_t sb = smem_u32(smem);
    const int tid = threadIdx.x, wid = tid >> 5, lane = tid & 31;
    const int head  = blockIdx.x;
    const int mt    = blockIdx.y;
    const int mtile = mt * 128;
    const int batch = mt >> 2;
    const int soff  = (mt & 3) * 128;
    const int wm  = (wid >> 1) * 32;
    const int wnA = (wid & 1) * 48;
    const int wn1 = (wid & 1) * 64;

    // ---- prefix-mask early exit (CTA-uniform branch) ----
    if (mask[batch * Sq + soff] < 0.5f) {
        if (tid < 96) {
            float* dst = &g_part[(size_t)mt * 3 * Cq + head * HDq + tid];
            dst[0]      = -1e30f;
            dst[Cq]     = 0.f;
            dst[2 * Cq] = 0.f;
        }
        return;
    }

    const __half* W1h = g_W1b + (size_t)head * HIDq * HDq;
    const __half* W2h = g_W2b + (size_t)head * HDq * HIDq;
    const float* b1h = b1 + head * HIDq;
    const float* b2h = b2 + head * HDq;

    // ======================= Phase A: projection GEMM ======================
    auto load_chunk = [&](int c, int s) {
        const int kb = c * 64;
        const uint32_t st = sb + OST + s * ASTG;
        #pragma unroll
        for (int t = 0; t < 4; t++) {              // X: 128 rows x 8 col16
            int idx = tid + t * 256;
            int row = idx >> 3, c16 = idx & 7;
            uint32_t off = SW(row * 128 + c16 * 16);
            cp16(st + off, Xh + (size_t)(mtile + row) * Dq + kb + c16 * 8);
        }
        #pragma unroll
        for (int t = 0; t < 3; t++) {              // P: 96 rows x 8 col16
            int idx = tid + t * 256;
            int row = idx >> 3, c16 = idx & 7;
            uint32_t off = SW(row * 128 + c16 * 16);
            cp16(st + 16384 + off, Ph + (size_t)(head * HDq + row) * Dq + kb + c16 * 8);
        }
        CP_COMMIT();
    };

    float accA[2][6][4];
    #pragma unroll
    for (int a = 0; a < 2; a++)
        #pragma unroll
        for (int b = 0; b < 6; b++)
            #pragma unroll
            for (int c = 0; c < 4; c++) accA[a][b][c] = 0.f;

    load_chunk(0, 0);
    #pragma unroll 1
    for (int c = 0; c < 12; c++) {
        if (c + 1 < 12) { load_chunk(c + 1, (c + 1) & 1); CP_WAIT(1); }
        else            { CP_WAIT(0); }
        __syncthreads();

        const uint32_t st  = sb + OST + (c & 1) * ASTG;
        const uint32_t sXh = st, sPh = st + 16384;
        #pragma unroll
        for (int ks = 0; ks < 4; ks++) {
            uint32_t ah[2][4], bh[3][4];
            #pragma unroll
            for (int mf = 0; mf < 2; mf++) {
                int row = wm + mf * 16 + (lane & 15);
                ldsm_x4(ah[mf], sXh + SW(row * 128 + ((lane >> 4) + ks * 2) * 16));
            }
            #pragma unroll
            for (int p = 0; p < 3; p++) {
                int g = lane >> 3;
                int row = wnA + p * 16 + (g >> 1) * 8 + (lane & 7);
                ldsm_x4(bh[p], sPh + SW(row * 128 + (ks * 2 + (g & 1)) * 16));
            }
            #pragma unroll
            for (int mf = 0; mf < 2; mf++)
                #pragma unroll
                for (int nf = 0; nf < 6; nf++)
                    mma16816(accA[mf][nf], ah[mf], &bh[nf >> 1][(nf & 1) * 2]);
        }
        __syncthreads();      // all MMAs on this stage done before overwrite
    }

    // W chunk prefetch (stage buffers dead; W dbuf overlaps them)
    auto load_w = [&](int jc) {
        const int j0 = jc * 128;
        const uint32_t w1d = sb + OW1 + (jc & 1) * W1SZ;
        const uint32_t w2d = sb + OW2 + (jc & 1) * W2SZ;
        #pragma unroll
        for (int t = 0; t < 6; t++) {
            int idx = tid + t * 256;
            int row = idx / 12, c16 = idx % 12;
            cp16(w1d + row * SHI + c16 * 16, W1h + (size_t)(j0 + row) * HDq + c16 * 8);
        }
        #pragma unroll
        for (int t = 0; t < 6; t++) {
            int idx = tid + t * 256;
            int row = idx >> 4, c16 = idx & 15;
            cp16(w2d + row * SF + c16 * 16, W2h + (size_t)row * HIDq + j0 + c16 * 8);
        }
        CP_COMMIT();
    };
    load_w(0);

    // Phase A epilogue: accA + bias -> Hi fp16 (OHH) and Hi fp32 (OAS)
    float* As = reinterpret_cast<float*>(smem + OAS);
    float* mk = reinterpret_cast<float*>(smem + OMK);
    #pragma unroll
    for (int mf = 0; mf < 2; mf++) {
        const int m0 = wm + mf * 16 + (lane >> 2);
        #pragma unroll
        for (int nf = 0; nf < 6; nf++) {
            const int n = wnA + nf * 8 + 2 * (lane & 3);
            const float c0 = __ldg(&bP[head * HDq + n]);
            const float c1 = __ldg(&bP[head * HDq + n + 1]);
            float v0 = accA[mf][nf][0] + c0, v1 = accA[mf][nf][1] + c1;
            float v2 = accA[mf][nf][2] + c0, v3 = accA[mf][nf][3] + c1;
            __half2 p0 = __floats2half2_rn(v0, v1);
            __half2 p1 = __floats2half2_rn(v2, v3);
            *reinterpret_cast<uint32_t*>(smem + OHH + m0 * SHI + n * 2) =
                *reinterpret_cast<uint32_t*>(&p0);
            *reinterpret_cast<uint32_t*>(smem + OHH + (m0 + 8) * SHI + n * 2) =
                *reinterpret_cast<uint32_t*>(&p1);
            As[m0 * 97 + n]           = v0;
            As[m0 * 97 + n + 1]       = v1;
            As[(m0 + 8) * 97 + n]     = v2;
            As[(m0 + 8) * 97 + n + 1] = v3;
        }
    }
    if (tid < 128) mk[tid] = mask[batch * Sq + soff + tid];
    __syncthreads();

    // ========================== Phase B: MLP ===============================
    float acc2[2][6][4];
    #pragma unroll
    for (int a = 0; a < 2; a++)
        #pragma unroll
        for (int b = 0; b < 6; b++)
            #pragma unroll
            for (int c = 0; c < 4; c++) acc2[a][b][c] = 0.f;

    #pragma unroll 1
    for (int jc = 0; jc < 3; jc++) {
        const int j0 = jc * 128;
        CP_WAIT(0);
        __syncthreads();
        if (jc + 1 < 3) load_w(jc + 1);

        const uint32_t w1b = sb + OW1 + (jc & 1) * W1SZ;
        const uint32_t w2b = sb + OW2 + (jc & 1) * W2SZ;

        float acc1[2][8][4];
        #pragma unroll
        for (int a = 0; a < 2; a++)
            #pragma unroll
            for (int b = 0; b < 8; b++)
                #pragma unroll
                for (int c = 0; c < 4; c++) acc1[a][b][c] = 0.f;

        #pragma unroll
        for (int ks = 0; ks < 6; ks++) {       // K = 96
            uint32_t afr[2][4], bfr[4][4];
            #pragma unroll
            for (int mf = 0; mf < 2; mf++) {
                int row = wm + mf * 16 + (lane & 15);
                ldsm_x4(afr[mf], sb + OHH + row * SHI + (lane >> 4) * 16 + ks * 32);
            }
            #pragma unroll
            for (int p = 0; p < 4; p++) {
                int g = lane >> 3;
                int row = wn1 + p * 16 + (g >> 1) * 8 + (lane & 7);
                ldsm_x4(bfr[p], w1b + row * SHI + (g & 1) * 16 + ks * 32);
            }
            #pragma unroll
            for (int mf = 0; mf < 2; mf++)
                #pragma unroll
                for (int nf = 0; nf < 8; nf++)
                    mma16816(acc1[mf][nf], afr[mf], &bfr[nf >> 1][(nf & 1) * 2]);
        }

        // relu + b1 -> F (fp16)
        #pragma unroll
        for (int mf = 0; mf < 2; mf++) {
            const int m0 = wm + mf * 16 + (lane >> 2);
            #pragma unroll
            for (int nf = 0; nf < 8; nf++) {
                const int jl = wn1 + nf * 8 + 2 * (lane & 3);
                const float c0 = __ldg(&b1h[j0 + jl]), c1 = __ldg(&b1h[j0 + jl + 1]);
                float v0 = fmaxf(acc1[mf][nf][0] + c0, 0.f);
                float v1 = fmaxf(acc1[mf][nf][1] + c1, 0.f);
                float v2 = fmaxf(acc1[mf][nf][2] + c0, 0.f);
                float v3 = fmaxf(acc1[mf][nf][3] + c1, 0.f);
                __half2 p0 = __floats2half2_rn(v0, v1);
                __half2 p1 = __floats2half2_rn(v2, v3);
                *reinterpret_cast<uint32_t*>(smem + OF + m0 * SF + jl * 2) =
                    *reinterpret_cast<uint32_t*>(&p0);
                *reinterpret_cast<uint32_t*>(smem + OF + (m0 + 8) * SF + jl * 2) =
                    *reinterpret_cast<uint32_t*>(&p1);
            }
        }
        __syncthreads();

        #pragma unroll
        for (int ks = 0; ks < 8; ks++) {       // K = 128
            uint32_t afr[2][4], bfr[3][4];
            #pragma unroll
            for (int mf = 0; mf < 2; mf++) {
                int row = wm + mf * 16 + (lane & 15);
                ldsm_x4(afr[mf], sb + OF + row * SF + (lane >> 4) * 16 + ks * 32);
            }
            #pragma unroll
            for (int p = 0; p < 3; p++) {
                int g = lane >> 3;
                int row = wnA + p * 16 + (g >> 1) * 8 + (lane & 7);
                ldsm_x4(bfr[p], w2b + row * SF + (g & 1) * 16 + ks * 32);
            }
            #pragma unroll
            for (int mf = 0; mf < 2; mf++)
                #pragma unroll
                for (int nf = 0; nf < 6; nf++)
                    mma16816(acc2[mf][nf], afr[mf], &bfr[nf >> 1][(nf & 1) * 2]);
        }
    }

    // ===================== Phase C: softmax-pool partials (FROZEN) =========
    __syncthreads();
    float* Lg = reinterpret_cast<float*>(smem + OW1);   // logits [128][97]
    #pragma unroll
    for (int mf = 0; mf < 2; mf++) {
        const int m0 = wm + mf * 16 + (lane >> 2);
        #pragma unroll
        for (int nf = 0; nf < 6; nf++) {
            const int n = wnA + nf * 8 + 2 * (lane & 3);
            const float c0 = __ldg(&b2h[n]), c1 = __ldg(&b2h[n + 1]);
            Lg[m0 * 97 + n]           = acc2[mf][nf][0] + c0;
            Lg[m0 * 97 + n + 1]       = acc2[mf][nf][1] + c1;
            Lg[(m0 + 8) * 97 + n]     = acc2[mf][nf][2] + c0;
            Lg[(m0 + 8) * 97 + n + 1] = acc2[mf][nf][3] + c1;
        }
    }
    __syncthreads();

    float* red = reinterpret_cast<float*>(smem + ORD);
    if (tid < 192) {
        const int ch = tid % 96, half = tid / 96;
        float m = -1e30f, l = 0.f, a = 0.f;
        for (int t = half * 64; t < half * 64 + 64; t++) {
            if (mk[t] > 0.5f) {
                float x  = Lg[t * 97 + ch];
                float hv = As[t * 97 + ch];
                float n  = fmaxf(m, x);
                float sc = fexp(m - n), w = fexp(x - n);
                l = fmaf(l, sc, w);
                a = fmaf(a, sc, w * hv);
                m = n;
            }
        }
        red[(half * 3 + 0) * 96 + ch] = m;
        red[(half * 3 + 1) * 96 + ch] = l;
        red[(half * 3 + 2) * 96 + ch] = a;
    }
    __syncthreads();
    if (tid < 96) {
        const int ch = tid;
        float m0 = red[0 * 96 + ch], l0 = red[1 * 96 + ch], a0 = red[2 * 96 + ch];
        float m1 = red[3 * 96 + ch], l1 = red[4 * 96 + ch], a1 = red[5 * 96 + ch];
        float n  = fmaxf(fmaxf(m0, m1), -1e30f);
        float s0 = fexp(m0 - n), s1 = fexp(m1 - n);
        float* dst = &g_part[(size_t)mt * 3 * Cq + head * HDq + ch];
        dst[0]      = n;
        dst[Cq]     = l0 * s0 + l1 * s1;
        dst[2 * Cq] = a0 * s0 + a1 * s1;
    }
}

// ---------------------------------------------------------------------------
// K3: merge 4 chunk partials per (batch, channel) -> output
// ---------------------------------------------------------------------------
__global__ __launch_bounds__(256) void k3_reduce(float* __restrict__ out)
{
    const int idx = blockIdx.x * 256 + threadIdx.x;
    const int b = idx / Cq, ch = idx % Cq;

    float m = -1e30f;
    #pragma unroll
    for (int c = 0; c < 4; c++)
        m = fmaxf(m, g_part[(size_t)(b * 4 + c) * 3 * Cq + ch]);

    float l = 0.f, a = 0.f;
    #pragma unroll
    for (int c = 0; c < 4; c++) {
        const float* p = &g_part[(size_t)(b * 4 + c) * 3 * Cq + ch];
        float s = fexp(p[0] - m);
        l = fmaf(p[Cq],     s, l);
        a = fmaf(p[2 * Cq], s, a);
    }
    out[idx] = a / l;
}

// ---------------------------------------------------------------------------
extern "C" void kernel_launch(void* const* d_in, const int* in_sizes, int n_in,
                              void* d_out, int out_size)
{
    const float* X    = (const float*)d_in[0];
    const float* mask = (const float*)d_in[1];
    const float* P    = (const float*)d_in[2];
    const float* bP   = (const float*)d_in[3];
    const float* W1   = (const float*)d_in[4];
    const float* b1   = (const float*)d_in[5];
    const float* W2   = (const float*)d_in[6];
    const float* b2   = (const float*)d_in[7];
    float* out = (float*)d_out;

    cudaFuncSetAttribute(kf_fused, cudaFuncAttributeMaxDynamicSharedMemorySize, KF_SMEM);

    __half *Xh, *Ph;
    cudaGetSymbolAddress((void**)&Xh, g_Xh);
    cudaGetSymbolAddress((void**)&Ph, g_Ph);

    // K0a: X convert to fp16
    {
        int n4x = Mq * Dq / 4;
        k0_cvtX<<<(n4x + 255) / 256, 256>>>(X, n4x);
    }
    // K0b: P + W converts in one launch
    {
        int ncells = N4P + 2 * N4W;
        k0_misc<<<(ncells + 255) / 256, 256>>>(P, W1, W2);
    }

    // KF: fused projection + MLP + partial softmax-pool (+ early exit)
    dim3 gf(NHq, Mq / 128);
    kf_fused<<<gf, 256, KF_SMEM>>>(Xh, Ph, bP, b1, b2, mask);

    // K3: merge partials
    k3_reduce<<<(Bq * Cq) / 256, 256>>>(out);
}

// round 15
// speedup vs baseline: 1.4104x; 1.2275x over previous
#include <cuda_runtime.h>
#include <cuda_bf16.h>
#include <cuda_fp16.h>
#include <math.h>
#include <stdint.h>

#define Bq   128
#define Sq   512
#define Dq   768
#define NHq  8
#define HDq  96
#define HIDq 384
#define Cq   768            // NH*HD
#define Mq   (Bq*Sq)        // 65536 tokens

// ---------------------------------------------------------------------------
// Scratch (__device__ globals; cudaMalloc is forbidden)
// ---------------------------------------------------------------------------
__device__ __half  g_Xh [(size_t)Mq * Dq];   // 96 MB X fp16
__device__ __half  g_Ph [(size_t)Cq * Dq];   // P fp16
__device__ __half  g_W1b[(size_t)NHq * HIDq * HDq];
__device__ __half  g_W2b[(size_t)NHq * HDq * HIDq];
__device__ float   g_part[(size_t)(Mq/128) * 3 * Cq];  // [mtile][{m,l,a}][768]

// ---------------------------------------------------------------------------
// Generic-PTX tensor-core helpers (plain sm_103 target safe)
// ---------------------------------------------------------------------------
__device__ __forceinline__ uint32_t smem_u32(const void* p) {
    uint32_t a;
    asm("{ .reg .u64 t; cvta.to.shared.u64 t, %1; cvt.u32.u64 %0, t; }"
        : "=r"(a) : "l"(p));
    return a;
}
__device__ __forceinline__ void mma16816(float* c, const uint32_t* a, const uint32_t* b) {
    asm volatile("mma.sync.aligned.m16n8k16.row.col.f32.f16.f16.f32 "
        "{%0,%1,%2,%3}, {%4,%5,%6,%7}, {%8,%9}, {%0,%1,%2,%3};"
        : "+f"(c[0]), "+f"(c[1]), "+f"(c[2]), "+f"(c[3])
        : "r"(a[0]), "r"(a[1]), "r"(a[2]), "r"(a[3]), "r"(b[0]), "r"(b[1]));
}
__device__ __forceinline__ void ldsm_x4(uint32_t* r, uint32_t addr) {
    asm volatile("ldmatrix.sync.aligned.m8n8.x4.shared.b16 {%0,%1,%2,%3}, [%4];"
        : "=r"(r[0]), "=r"(r[1]), "=r"(r[2]), "=r"(r[3]) : "r"(addr));
}
__device__ __forceinline__ void cp16(uint32_t dst, const void* src) {
    asm volatile("cp.async.cg.shared.global [%0], [%1], 16;" :: "r"(dst), "l"(src));
}
#define CP_COMMIT()  asm volatile("cp.async.commit_group;" ::: "memory")
#define CP_WAIT(n)   asm volatile("cp.async.wait_group %0;" :: "n"(n) : "memory")
#define SW(o)        ((o) ^ (((o) >> 3) & 0x70))

__device__ __forceinline__ float fexp(float x) {
    x = fmaxf(x, -80.f);
    float t  = x * 1.4426950408889634f;
    float fi = floorf(t);
    float f  = t - fi;
    float p  = 1.8775767e-3f;
    p = fmaf(p, f, 8.9893397e-3f);
    p = fmaf(p, f, 5.5826318e-2f);
    p = fmaf(p, f, 2.4015361e-1f);
    p = fmaf(p, f, 6.9315308e-1f);
    p = fmaf(p, f, 1.0f);
    return __int_as_float(__float_as_int(p) + (((int)fi) << 23));
}

// ---------------------------------------------------------------------------
// K0a: X fp32 -> fp16 convert
// ---------------------------------------------------------------------------
__global__ __launch_bounds__(256) void k0_cvtX(
    const float* __restrict__ src, int n4)
{
    int i = blockIdx.x * 256 + threadIdx.x;
    if (i >= n4) return;
    float4 v = reinterpret_cast<const float4*>(src)[i];
    ushort4 H;
    H.x = __half_as_ushort(__float2half_rn(v.x));
    H.y = __half_as_ushort(__float2half_rn(v.y));
    H.z = __half_as_ushort(__float2half_rn(v.z));
    H.w = __half_as_ushort(__float2half_rn(v.w));
    reinterpret_cast<ushort4*>(g_Xh)[i] = H;
}

// ---------------------------------------------------------------------------
// K0b: P + W1 + W2 fp32 -> fp16 convert in one launch
// ---------------------------------------------------------------------------
#define N4P (Cq * Dq / 4)
#define N4W (NHq * HIDq * HDq / 4)

__global__ __launch_bounds__(256) void k0_misc(
    const float* __restrict__ P, const float* __restrict__ W1,
    const float* __restrict__ W2)
{
    int i = blockIdx.x * 256 + threadIdx.x;
    const float* src;
    __half* dst;
    if (i < N4P)            { src = P;  dst = g_Ph; }
    else {
        i -= N4P;
        if (i < N4W)        { src = W1; dst = g_W1b; }
        else                { i -= N4W; if (i >= N4W) return; src = W2; dst = g_W2b; }
    }
    float4 v = reinterpret_cast<const float4*>(src)[i];
    ushort4 H;
    H.x = __half_as_ushort(__float2half_rn(v.x));
    H.y = __half_as_ushort(__float2half_rn(v.y));
    H.z = __half_as_ushort(__float2half_rn(v.z));
    H.w = __half_as_ushort(__float2half_rn(v.w));
    reinterpret_cast<ushort4*>(dst)[i] = H;
}

// ---------------------------------------------------------------------------
// KF: fused per-(head, 128-token tile) kernel — 96 KB smem, 2 CTAs/SM.
//   Phase A: Hi = X @ P_h^T + bP (fp16 HMMA, 12 K-chunks, 2-stage pipeline)
//   Phase B: logits via 4 hidden-chunks of 96, single-buffered W tiles
//   Phase C: masked softmax-pool partials, Hi read back as fp16.
// smem map: OHH 0 (26624 Hi fp16 [128][208]) | OMK 26624 (512) |
//           ORD 27136 (2304) | OB 29440 (66560 shared region):
//             Phase A: 2 stages x 28672 (Xh 16384 | Ph 12288)
//             Phase B: F[128][208]@OB, W1c[96][208]@+26624, W2c[96][208]@+46592
//             Phase C: Lg fp32 [128][97]@OB (49664)
// ---------------------------------------------------------------------------
#define OHH   0
#define OMK   26624
#define ORD   27136
#define OB    29440
#define ASTG  28672
#define OF    OB
#define OW1   (OB + 26624)
#define OW2   (OB + 46592)
#define KF_SMEM 96000
#define SHI   208

__global__ __launch_bounds__(256, 2) void kf_fused(
    const __half* __restrict__ Xh, const __half* __restrict__ Ph,
    const float* __restrict__ bP,
    const float* __restrict__ b1, const float* __restrict__ b2,
    const float* __restrict__ mask)
{
    extern __shared__ char smem[];
    const uint32_t sb = smem_u32(smem);
    const int tid = threadIdx.x, wid = tid >> 5, lane = tid & 31;
    const int head  = blockIdx.x;
    const int mt    = blockIdx.y;
    const int mtile = mt * 128;
    const int batch = mt >> 2;
    const int soff  = (mt & 3) * 128;
    const int wm  = (wid >> 1) * 32;
    const int wnA = (wid & 1) * 48;    // N=96 split for Phase A / B layers

    // ---- prefix-mask early exit (CTA-uniform branch) ----
    if (mask[batch * Sq + soff] < 0.5f) {
        if (tid < 96) {
            float* dst = &g_part[(size_t)mt * 3 * Cq + head * HDq + tid];
            dst[0]      = -1e30f;
            dst[Cq]     = 0.f;
            dst[2 * Cq] = 0.f;
        }
        return;
    }

    const __half* W1h = g_W1b + (size_t)head * HIDq * HDq;
    const __half* W2h = g_W2b + (size_t)head * HDq * HIDq;
    const float* b1h = b1 + head * HIDq;
    const float* b2h = b2 + head * HDq;

    // ======================= Phase A: projection GEMM ======================
    auto load_chunk = [&](int c, int s) {
        const int kb = c * 64;
        const uint32_t st = sb + OB + s * ASTG;
        #pragma unroll
        for (int t = 0; t < 4; t++) {              // X: 128 rows x 8 col16
            int idx = tid + t * 256;
            int row = idx >> 3, c16 = idx & 7;
            uint32_t off = SW(row * 128 + c16 * 16);
            cp16(st + off, Xh + (size_t)(mtile + row) * Dq + kb + c16 * 8);
        }
        #pragma unroll
        for (int t = 0; t < 3; t++) {              // P: 96 rows x 8 col16
            int idx = tid + t * 256;
            int row = idx >> 3, c16 = idx & 7;
            uint32_t off = SW(row * 128 + c16 * 16);
            cp16(st + 16384 + off, Ph + (size_t)(head * HDq + row) * Dq + kb + c16 * 8);
        }
        CP_COMMIT();
    };

    float accA[2][6][4];
    #pragma unroll
    for (int a = 0; a < 2; a++)
        #pragma unroll
        for (int b = 0; b < 6; b++)
            #pragma unroll
            for (int c = 0; c < 4; c++) accA[a][b][c] = 0.f;

    load_chunk(0, 0);
    #pragma unroll 1
    for (int c = 0; c < 12; c++) {
        if (c + 1 < 12) { load_chunk(c + 1, (c + 1) & 1); CP_WAIT(1); }
        else            { CP_WAIT(0); }
        __syncthreads();

        const uint32_t st  = sb + OB + (c & 1) * ASTG;
        const uint32_t sXh = st, sPh = st + 16384;
        #pragma unroll
        for (int ks = 0; ks < 4; ks++) {
            uint32_t ah[2][4], bh[3][4];
            #pragma unroll
            for (int mf = 0; mf < 2; mf++) {
                int row = wm + mf * 16 + (lane & 15);
                ldsm_x4(ah[mf], sXh + SW(row * 128 + ((lane >> 4) + ks * 2) * 16));
            }
            #pragma unroll
            for (int p = 0; p < 3; p++) {
                int g = lane >> 3;
                int row = wnA + p * 16 + (g >> 1) * 8 + (lane & 7);
                ldsm_x4(bh[p], sPh + SW(row * 128 + (ks * 2 + (g & 1)) * 16));
            }
            #pragma unroll
            for (int mf = 0; mf < 2; mf++)
                #pragma unroll
                for (int nf = 0; nf < 6; nf++)
                    mma16816(accA[mf][nf], ah[mf], &bh[nf >> 1][(nf & 1) * 2]);
        }
        __syncthreads();      // all MMAs on this stage done before overwrite
    }

    // Phase A epilogue: accA + bias -> Hi fp16 (OHH); stage mask
    float* mk = reinterpret_cast<float*>(smem + OMK);
    #pragma unroll
    for (int mf = 0; mf < 2; mf++) {
        const int m0 = wm + mf * 16 + (lane >> 2);
        #pragma unroll
        for (int nf = 0; nf < 6; nf++) {
            const int n = wnA + nf * 8 + 2 * (lane & 3);
            const float c0 = __ldg(&bP[head * HDq + n]);
            const float c1 = __ldg(&bP[head * HDq + n + 1]);
            __half2 p0 = __floats2half2_rn(accA[mf][nf][0] + c0, accA[mf][nf][1] + c1);
            __half2 p1 = __floats2half2_rn(accA[mf][nf][2] + c0, accA[mf][nf][3] + c1);
            *reinterpret_cast<uint32_t*>(smem + OHH + m0 * SHI + n * 2) =
                *reinterpret_cast<uint32_t*>(&p0);
            *reinterpret_cast<uint32_t*>(smem + OHH + (m0 + 8) * SHI + n * 2) =
                *reinterpret_cast<uint32_t*>(&p1);
        }
    }
    if (tid < 128) mk[tid] = mask[batch * Sq + soff + tid];

    // ========== Phase B: MLP, 4 hidden chunks of 96, single W buffer =======
    auto load_w = [&](int jc) {
        const int j0 = jc * 96;
        #pragma unroll
        for (int t = 0; t < 5; t++) {              // W1c: 96 x 96 = 1152 cells
            int idx = tid + t * 256;
            if (idx < 1152) {
                int row = idx / 12, c16 = idx % 12;
                cp16(sb + OW1 + row * SHI + c16 * 16,
                     W1h + (size_t)(j0 + row) * HDq + c16 * 8);
            }
        }
        #pragma unroll
        for (int t = 0; t < 5; t++) {              // W2c: 96 x 96 = 1152 cells
            int idx = tid + t * 256;
            if (idx < 1152) {
                int row = idx / 12, c16 = idx % 12;
                cp16(sb + OW2 + row * SHI + c16 * 16,
                     W2h + (size_t)row * HIDq + j0 + c16 * 8);
            }
        }
        CP_COMMIT();
    };

    float acc2[2][6][4];
    #pragma unroll
    for (int a = 0; a < 2; a++)
        #pragma unroll
        for (int b = 0; b < 6; b++)
            #pragma unroll
            for (int c = 0; c < 4; c++) acc2[a][b][c] = 0.f;

    #pragma unroll 1
    for (int jc = 0; jc < 4; jc++) {
        const int j0 = jc * 96;
        __syncthreads();            // prev chunk's W/F reads done; OHH visible (jc=0)
        load_w(jc);
        CP_WAIT(0);
        __syncthreads();            // W chunk visible

        float acc1[2][6][4];
        #pragma unroll
        for (int a = 0; a < 2; a++)
            #pragma unroll
            for (int b = 0; b < 6; b++)
                #pragma unroll
                for (int c = 0; c < 4; c++) acc1[a][b][c] = 0.f;

        // ---- layer 1: F = relu(Hi @ W1c^T + b1), K=96, N=96 ----
        #pragma unroll
        for (int ks = 0; ks < 6; ks++) {
            uint32_t afr[2][4], bfr[3][4];
            #pragma unroll
            for (int mf = 0; mf < 2; mf++) {
                int row = wm + mf * 16 + (lane & 15);
                ldsm_x4(afr[mf], sb + OHH + row * SHI + (lane >> 4) * 16 + ks * 32);
            }
            #pragma unroll
            for (int p = 0; p < 3; p++) {
                int g = lane >> 3;
                int row = wnA + p * 16 + (g >> 1) * 8 + (lane & 7);
                ldsm_x4(bfr[p], sb + OW1 + row * SHI + (g & 1) * 16 + ks * 32);
            }
            #pragma unroll
            for (int mf = 0; mf < 2; mf++)
                #pragma unroll
                for (int nf = 0; nf < 6; nf++)
                    mma16816(acc1[mf][nf], afr[mf], &bfr[nf >> 1][(nf & 1) * 2]);
        }

        // relu + b1 -> F (fp16)
        #pragma unroll
        for (int mf = 0; mf < 2; mf++) {
            const int m0 = wm + mf * 16 + (lane >> 2);
            #pragma unroll
            for (int nf = 0; nf < 6; nf++) {
                const int jl = wnA + nf * 8 + 2 * (lane & 3);
                const float c0 = __ldg(&b1h[j0 + jl]), c1 = __ldg(&b1h[j0 + jl + 1]);
                __half2 p0 = __floats2half2_rn(fmaxf(acc1[mf][nf][0] + c0, 0.f),
                                               fmaxf(acc1[mf][nf][1] + c1, 0.f));
                __half2 p1 = __floats2half2_rn(fmaxf(acc1[mf][nf][2] + c0, 0.f),
                                               fmaxf(acc1[mf][nf][3] + c1, 0.f));
                *reinterpret_cast<uint32_t*>(smem + OF + m0 * SHI + jl * 2) =
                    *reinterpret_cast<uint32_t*>(&p0);
                *reinterpret_cast<uint32_t*>(smem + OF + (m0 + 8) * SHI + jl * 2) =
                    *reinterpret_cast<uint32_t*>(&p1);
            }
        }
        __syncthreads();            // F visible

        // ---- layer 2 partial: acc2 += F @ W2c^T, K=96, N=96 ----
        #pragma unroll
        for (int ks = 0; ks < 6; ks++) {
            uint32_t afr[2][4], bfr[3][4];
            #pragma unroll
            for (int mf = 0; mf < 2; mf++) {
                int row = wm + mf * 16 + (lane & 15);
                ldsm_x4(afr[mf], sb + OF + row * SHI + (lane >> 4) * 16 + ks * 32);
            }
            #pragma unroll
            for (int p = 0; p < 3; p++) {
                int g = lane >> 3;
                int row = wnA + p * 16 + (g >> 1) * 8 + (lane & 7);
                ldsm_x4(bfr[p], sb + OW2 + row * SHI + (g & 1) * 16 + ks * 32);
            }
            #pragma unroll
            for (int mf = 0; mf < 2; mf++)
                #pragma unroll
                for (int nf = 0; nf < 6; nf++)
                    mma16816(acc2[mf][nf], afr[mf], &bfr[nf >> 1][(nf & 1) * 2]);
        }
    }

    // ===================== Phase C: softmax-pool partials ==================
    __syncthreads();                // last L2 MMAs done; OB region reusable
    float* Lg = reinterpret_cast<float*>(smem + OB);    // logits [128][97]
    #pragma unroll
    for (int mf = 0; mf < 2; mf++) {
        const int m0 = wm + mf * 16 + (lane >> 2);
        #pragma unroll
        for (int nf = 0; nf < 6; nf++) {
            const int n = wnA + nf * 8 + 2 * (lane & 3);
            const float c0 = __ldg(&b2h[n]), c1 = __ldg(&b2h[n + 1]);
            Lg[m0 * 97 + n]           = acc2[mf][nf][0] + c0;
            Lg[m0 * 97 + n + 1]       = acc2[mf][nf][1] + c1;
            Lg[(m0 + 8) * 97 + n]     = acc2[mf][nf][2] + c0;
            Lg[(m0 + 8) * 97 + n + 1] = acc2[mf][nf][3] + c1;
        }
    }
    __syncthreads();

    float* red = reinterpret_cast<float*>(smem + ORD);
    if (tid < 192) {
        const int ch = tid % 96, half = tid / 96;
        float m = -1e30f, l = 0.f, a = 0.f;
        for (int t = half * 64; t < half * 64 + 64; t++) {
            if (mk[t] > 0.5f) {
                float x  = Lg[t * 97 + ch];
                float hv = __half2float(*reinterpret_cast<const __half*>(
                               smem + OHH + t * SHI + ch * 2));
                float n  = fmaxf(m, x);
                float sc = fexp(m - n), w = fexp(x - n);
                l = fmaf(l, sc, w);
                a = fmaf(a, sc, w * hv);
                m = n;
            }
        }
        red[(half * 3 + 0) * 96 + ch] = m;
        red[(half * 3 + 1) * 96 + ch] = l;
        red[(half * 3 + 2) * 96 + ch] = a;
    }
    __syncthreads();
    if (tid < 96) {
        const int ch = tid;
        float m0 = red[0 * 96 + ch], l0 = red[1 * 96 + ch], a0 = red[2 * 96 + ch];
        float m1 = red[3 * 96 + ch], l1 = red[4 * 96 + ch], a1 = red[5 * 96 + ch];
        float n  = fmaxf(fmaxf(m0, m1), -1e30f);
        float s0 = fexp(m0 - n), s1 = fexp(m1 - n);
        float* dst = &g_part[(size_t)mt * 3 * Cq + head * HDq + ch];
        dst[0]      = n;
        dst[Cq]     = l0 * s0 + l1 * s1;
        dst[2 * Cq] = a0 * s0 + a1 * s1;
    }
}

// ---------------------------------------------------------------------------
// K3: merge 4 chunk partials per (batch, channel) -> output
// ---------------------------------------------------------------------------
__global__ __launch_bounds__(256) void k3_reduce(float* __restrict__ out)
{
    const int idx = blockIdx.x * 256 + threadIdx.x;
    const int b = idx / Cq, ch = idx % Cq;

    float m = -1e30f;
    #pragma unroll
    for (int c = 0; c < 4; c++)
        m = fmaxf(m, g_part[(size_t)(b * 4 + c) * 3 * Cq + ch]);

    float l = 0.f, a = 0.f;
    #pragma unroll
    for (int c = 0; c < 4; c++) {
        const float* p = &g_part[(size_t)(b * 4 + c) * 3 * Cq + ch];
        float s = fexp(p[0] - m);
        l = fmaf(p[Cq],     s, l);
        a = fmaf(p[2 * Cq], s, a);
    }
    out[idx] = a / l;
}

// ---------------------------------------------------------------------------
extern "C" void kernel_launch(void* const* d_in, const int* in_sizes, int n_in,
                              void* d_out, int out_size)
{
    const float* X    = (const float*)d_in[0];
    const float* mask = (const float*)d_in[1];
    const float* P    = (const float*)d_in[2];
    const float* bP   = (const float*)d_in[3];
    const float* W1   = (const float*)d_in[4];
    const float* b1   = (const float*)d_in[5];
    const float* W2   = (const float*)d_in[6];
    const float* b2   = (const float*)d_in[7];
    float* out = (float*)d_out;

    cudaFuncSetAttribute(kf_fused, cudaFuncAttributeMaxDynamicSharedMemorySize, KF_SMEM);

    __half *Xh, *Ph;
    cudaGetSymbolAddress((void**)&Xh, g_Xh);
    cudaGetSymbolAddress((void**)&Ph, g_Ph);

    // K0a: X convert to fp16
    {
        int n4x = Mq * Dq / 4;
        k0_cvtX<<<(n4x + 255) / 256, 256>>>(X, n4x);
    }
    // K0b: P + W converts in one launch
    {
        int ncells = N4P + 2 * N4W;
        k0_misc<<<(ncells + 255) / 256, 256>>>(P, W1, W2);
    }

    // KF: fused projection + MLP + partial softmax-pool (2 CTAs/SM)
    dim3 gf(NHq, Mq / 128);
    kf_fused<<<gf, 256, KF_SMEM>>>(Xh, Ph, bP, b1, b2, mask);

    // K3: merge partials
    k3_reduce<<<(Bq * Cq) / 256, 256>>>(out);
}